// round 1
// baseline (speedup 1.0000x reference)
#include <cuda_runtime.h>

#define EPS 1e-5f

// ---------------- scratch (no allocations allowed) ----------------
static __device__ float g_featC[2 * 128 * 400];            // [b][c][i]  (c-major "flatfeat")
static __device__ float g_scores[2 * 400 * 400];           // [b][s][p]
static __device__ float g_W2sum[9 * 128 * 128];            // [cls][o_in][o_out]
static __device__ __align__(16) float g_wr2T[128 * 9 * 128]; // [o_in][tap][o_out]
static __device__ float g_w2T[128 * 128];                  // [c][co]

__device__ __forceinline__ float silu_f(float y) {
    return y * (1.0f / (1.0f + __expf(-y)));
}

// ---------------- prep: weight rearrangements ----------------
__global__ void prep_kernel(const float* __restrict__ wr2, const float* __restrict__ w2) {
    int t = blockIdx.x * blockDim.x + threadIdx.x;
    if (t >= 128 * 128) return;
    int op = t >> 7;   // output channel o'
    int o  = t & 127;  // input channel o
    float w[9];
#pragma unroll
    for (int tap = 0; tap < 9; tap++) {
        w[tap] = wr2[(op * 128 + o) * 9 + tap];
        g_wr2T[(o * 9 + tap) * 128 + op] = w[tap];
    }
#pragma unroll
    for (int hc = 0; hc < 3; hc++) {
#pragma unroll
        for (int wc = 0; wc < 3; wc++) {
            float s = 0.f;
#pragma unroll
            for (int dh = 0; dh < 3; dh++) {
                if (hc == 0 && dh == 0) continue;
                if (hc == 2 && dh == 2) continue;
#pragma unroll
                for (int dw = 0; dw < 3; dw++) {
                    if (wc == 0 && dw == 0) continue;
                    if (wc == 2 && dw == 2) continue;
                    s += w[dh * 3 + dw];
                }
            }
            g_W2sum[((hc * 3 + wc) * 128 + o) * 128 + op] = s;
        }
    }
    // w2T[c][co] = w2[co][c]  (reuse o'=co, o=c)
    g_w2T[o * 128 + op] = w2[op * 128 + o];
}

// ---------------- feat = CBS(x, w1) into channel-major layout ----------------
__global__ void feat_kernel(const float* __restrict__ x, const float* __restrict__ w1,
                            const float* __restrict__ g1, const float* __restrict__ b1,
                            const float* __restrict__ m1, const float* __restrict__ v1) {
    __shared__ float wrow[128];
    int bc = blockIdx.x;           // 0..255
    int b = bc >> 7, c = bc & 127;
    int tid = threadIdx.x;         // 128
    wrow[tid] = w1[c * 128 + tid];
    __syncthreads();
    float a  = g1[c] * rsqrtf(v1[c] + EPS);
    float cc = b1[c] - m1[c] * a;
    for (int i = tid; i < 400; i += 128) {
        float s = 0.f;
#pragma unroll 8
        for (int cin = 0; cin < 128; cin++)
            s += wrow[cin] * x[(b * 128 + cin) * 400 + i];
        g_featC[(b * 128 + c) * 400 + i] = silu_f(a * s + cc);
    }
}

// ---------------- samples s < 200 : all channels constant over space ----------------
// out1 is spatially constant -> r2 output has only 9 distinct values (padding classes).
__global__ void const_kernel(const float* __restrict__ wr1,
                             const float* __restrict__ gr1, const float* __restrict__ br1,
                             const float* __restrict__ mr1, const float* __restrict__ vr1,
                             const float* __restrict__ gr2, const float* __restrict__ br2,
                             const float* __restrict__ mr2, const float* __restrict__ vr2,
                             const float* __restrict__ wr3,
                             const float* __restrict__ gr3, const float* __restrict__ br3,
                             const float* __restrict__ mr3, const float* __restrict__ vr3) {
    extern __shared__ float sm[];
    float* wr1s = sm;                    // 128 * 257 (padded rows, conflict-free)
    float* fwin = wr1s + 128 * 257;      // 256
    float* vbuf = fwin + 256;            // 128
    float* zbuf = vbuf + 128;            // 128
    float* scb  = zbuf + 128;            // 16 (9 used)

    int blk = blockIdx.x;                // 400 = 2 b * 200 s
    int b = blk / 200, s = blk % 200;
    int tid = threadIdx.x;               // 128

    for (int idx = tid; idx < 128 * 256; idx += 128) {
        int o = idx >> 8, u = idx & 255;
        wr1s[o * 257 + u] = wr1[idx];
    }
    fwin[tid]       = g_featC[b * 51200 + s * 256 + tid];
    fwin[tid + 128] = g_featC[b * 51200 + s * 256 + 128 + tid];
    __syncthreads();

    int o = tid;
    float K = 0.f;
#pragma unroll 8
    for (int u = 0; u < 256; u++) K += wr1s[o * 257 + u] * fwin[u];
    float a1 = gr1[o] * rsqrtf(vr1[o] + EPS);
    float c1 = br1[o] - mr1[o] * a1;
    vbuf[o] = silu_f(a1 * K + c1);
    __syncthreads();

    float a2 = gr2[o] * rsqrtf(vr2[o] + EPS);
    float c2 = br2[o] - mr2[o] * a2;
    float w3 = wr3[o];
    float a3 = gr3[0] * rsqrtf(vr3[0] + EPS);
    float c3 = br3[0] - mr3[0] * a3;

    for (int cls = 0; cls < 9; cls++) {
        float z = 0.f;
#pragma unroll 8
        for (int oo = 0; oo < 128; oo++)
            z += g_W2sum[(cls * 128 + oo) * 128 + o] * vbuf[oo];
        float zz = silu_f(a2 * z + c2);
        zbuf[o] = w3 * zz;
        __syncthreads();
        for (int off = 64; off > 0; off >>= 1) {
            if (o < off) zbuf[o] += zbuf[o + off];
            __syncthreads();
        }
        if (o == 0) scb[cls] = silu_f(a3 * zbuf[0] + c3);
        __syncthreads();
    }

    for (int p = tid; p < 400; p += 128) {
        int h = p / 20, w = p % 20;
        int hc = (h == 0) ? 0 : ((h == 19) ? 2 : 1);
        int wc = (w == 0) ? 0 : ((w == 19) ? 2 : 1);
        g_scores[(b * 400 + s) * 400 + p] = scb[hc * 3 + wc];
    }
}

// ---------------- samples s >= 200 : rank-2 spatial input, full 3x3 conv ----------------
__global__ __launch_bounds__(256, 1)
void spatial_kernel(const float* __restrict__ wr1,
                    const float* __restrict__ gr1, const float* __restrict__ br1,
                    const float* __restrict__ mr1, const float* __restrict__ vr1,
                    const float* __restrict__ gr2, const float* __restrict__ br2,
                    const float* __restrict__ mr2, const float* __restrict__ vr2,
                    const float* __restrict__ wr3,
                    const float* __restrict__ gr3, const float* __restrict__ br3,
                    const float* __restrict__ mr3, const float* __restrict__ vr3) {
    extern __shared__ float sm[];
    float* y1s = sm;                 // 128*400
    float* fA  = y1s + 128 * 400;    // 400
    float* fB  = fA + 400;           // 400
    float* al  = fB + 400;           // 128
    float* be  = al + 128;           // 128
    float* a1s = be + 128;           // 128
    float* c1s = a1s + 128;          // 128
    float* a2s = c1s + 128;          // 128
    float* c2s = a2s + 128;          // 128

    int blk = blockIdx.x;            // 400 = 2 b * 200 s
    int b = blk / 200;
    int s = 200 + blk % 200;
    int tid = threadIdx.x;           // 256

    int t0 = s * 256;
    int r0 = t0 % 400;
    int usplit = 400 - r0;
    if (usplit > 256) usplit = 256;
    int chA = t0 / 400 - 128;
    int chB = (usplit >= 256) ? chA : (chA + 1);

    if (tid < 128) {
        // alpha[o] = sum of wr1[o][u] for u < usplit  (those c2 map to channel chA)
        float a = 0.f;
#pragma unroll 8
        for (int u = 0; u < usplit; u++) a += wr1[tid * 256 + u];
        al[tid] = a;
    } else {
        int o = tid - 128;
        float bs = 0.f;
        for (int u = usplit; u < 256; u++) bs += wr1[o * 256 + u];
        be[o] = bs;
        float a1 = gr1[o] * rsqrtf(vr1[o] + EPS);
        a1s[o] = a1;
        c1s[o] = br1[o] - mr1[o] * a1;
        float a2 = gr2[o] * rsqrtf(vr2[o] + EPS);
        a2s[o] = a2;
        c2s[o] = br2[o] - mr2[o] * a2;
    }
    for (int p = tid; p < 400; p += 256) {
        fA[p] = g_featC[b * 51200 + chA * 400 + p];
        fB[p] = g_featC[b * 51200 + chB * 400 + p];
    }
    __syncthreads();

    // y1[o][p] = silu(bn1(alpha*fA + beta*fB))
    for (int idx = tid; idx < 128 * 400; idx += 256) {
        int o = idx / 400, p = idx - o * 400;
        float pre = a1s[o] * (al[o] * fA[p] + be[o] * fB[p]) + c1s[o];
        y1s[idx] = silu_f(pre);
    }
    __syncthreads();

    // 3x3 conv 128->128 + bn2 + silu + r3(128->1) + bn3 + silu -> scores
    int og = tid & 15;        // 16 groups of 8 output channels
    int wg = (tid >> 4) & 3;  // 4 groups of 5 columns
    int hb = tid >> 6;        // 4 base rows
    int o0 = og * 8;
    int w0 = wg * 5;
    float a3 = gr3[0] * rsqrtf(vr3[0] + EPS);
    float c3 = br3[0] - mr3[0] * a3;
    const float4* wt4 = reinterpret_cast<const float4*>(g_wr2T);
    float w3v[8];
#pragma unroll
    for (int oo = 0; oo < 8; oo++) w3v[oo] = wr3[o0 + oo];

    for (int it = 0; it < 5; it++) {
        int h = hb + it * 4;
        float acc[8][5];
#pragma unroll
        for (int oo = 0; oo < 8; oo++)
#pragma unroll
            for (int k = 0; k < 5; k++) acc[oo][k] = 0.f;

        for (int o = 0; o < 128; o++) {
            float yr[3][7];
#pragma unroll
            for (int dh = 0; dh < 3; dh++) {
                int row = h + dh - 1;
                int rowc = min(max(row, 0), 19);
                bool rv = (row >= 0) & (row < 20);
#pragma unroll
                for (int j = 0; j < 7; j++) {
                    int col = w0 - 1 + j;
                    int colc = min(max(col, 0), 19);
                    float v = y1s[o * 400 + rowc * 20 + colc];
                    yr[dh][j] = (rv && col >= 0 && col < 20) ? v : 0.f;
                }
            }
#pragma unroll
            for (int dh = 0; dh < 3; dh++) {
#pragma unroll
                for (int dw = 0; dw < 3; dw++) {
                    int base = ((o * 9 + dh * 3 + dw) * 128 + o0) >> 2;
                    float4 wa = wt4[base];
                    float4 wb = wt4[base + 1];
                    float wv[8] = {wa.x, wa.y, wa.z, wa.w, wb.x, wb.y, wb.z, wb.w};
#pragma unroll
                    for (int k = 0; k < 5; k++) {
                        float yv = yr[dh][dw + k];
#pragma unroll
                        for (int oo = 0; oo < 8; oo++) acc[oo][k] += wv[oo] * yv;
                    }
                }
            }
        }

#pragma unroll
        for (int k = 0; k < 5; k++) {
            float part = 0.f;
#pragma unroll
            for (int oo = 0; oo < 8; oo++) {
                float z = silu_f(a2s[o0 + oo] * acc[oo][k] + c2s[o0 + oo]);
                part += w3v[oo] * z;
            }
#pragma unroll
            for (int m = 8; m > 0; m >>= 1)
                part += __shfl_xor_sync(0xffffffffu, part, m, 16);
            if (og == 0) {
                int p = h * 20 + w0 + k;
                g_scores[(b * 400 + s) * 400 + p] = silu_f(a3 * part + c3);
            }
        }
    }
}

// ---------------- attention bmm + conv2(1x1)+bn+silu + residual ----------------
__global__ void att_kernel(const float* __restrict__ x,
                           const float* __restrict__ g2, const float* __restrict__ b2,
                           const float* __restrict__ m2, const float* __restrict__ v2,
                           float* __restrict__ out) {
    extern __shared__ float sm[];
    float* featCs = sm;                    // 128*401 (padded)
    float* srow   = featCs + 128 * 401;    // 400
    float* atts   = srow + 400;            // 128

    int blk = blockIdx.x;                  // 100 = 2 b * 50 chunks
    int b = blk / 50;
    int ib = (blk % 50) * 8;
    int tid = threadIdx.x;                 // 128

    for (int idx = tid; idx < 128 * 400; idx += 128) {
        int c = idx / 400, j = idx - c * 400;
        featCs[c * 401 + j] = g_featC[b * 51200 + idx];
    }
    __syncthreads();

    float a  = g2[tid] * rsqrtf(v2[tid] + EPS);
    float cc = b2[tid] - m2[tid] * a;

    for (int r = 0; r < 8; r++) {
        int i = ib + r;
        __syncthreads();
        for (int j = tid; j < 400; j += 128)
            srow[j] = g_scores[(b * 400 + i) * 400 + j];
        __syncthreads();
        int c = tid;
        float acc = 0.f;
#pragma unroll 8
        for (int j = 0; j < 400; j++) acc += srow[j] * featCs[c * 401 + j];
        atts[c] = acc;
        __syncthreads();
        int co = tid;
        float y = 0.f;
#pragma unroll 8
        for (int k = 0; k < 128; k++) y += g_w2T[k * 128 + co] * atts[k];
        out[(b * 128 + co) * 400 + i] = silu_f(a * y + cc) + x[(b * 128 + co) * 400 + i];
    }
}

// ---------------- launcher ----------------
extern "C" void kernel_launch(void* const* d_in, const int* in_sizes, int n_in,
                              void* d_out, int out_size) {
    (void)in_sizes; (void)n_in; (void)out_size;
    const float* x   = (const float*)d_in[0];
    const float* w1  = (const float*)d_in[1];
    const float* g1  = (const float*)d_in[2];
    const float* b1  = (const float*)d_in[3];
    const float* m1  = (const float*)d_in[4];
    const float* v1  = (const float*)d_in[5];
    const float* w2  = (const float*)d_in[6];
    const float* g2  = (const float*)d_in[7];
    const float* b2  = (const float*)d_in[8];
    const float* m2  = (const float*)d_in[9];
    const float* v2  = (const float*)d_in[10];
    const float* wr1 = (const float*)d_in[11];
    const float* gr1 = (const float*)d_in[12];
    const float* br1 = (const float*)d_in[13];
    const float* mr1 = (const float*)d_in[14];
    const float* vr1 = (const float*)d_in[15];
    const float* wr2 = (const float*)d_in[16];
    const float* gr2 = (const float*)d_in[17];
    const float* br2 = (const float*)d_in[18];
    const float* mr2 = (const float*)d_in[19];
    const float* vr2 = (const float*)d_in[20];
    const float* wr3 = (const float*)d_in[21];
    const float* gr3 = (const float*)d_in[22];
    const float* br3 = (const float*)d_in[23];
    const float* mr3 = (const float*)d_in[24];
    const float* vr3 = (const float*)d_in[25];
    float* out = (float*)d_out;

    const size_t sm_const   = (size_t)(128 * 257 + 256 + 128 + 128 + 16) * sizeof(float);
    const size_t sm_spatial = (size_t)(128 * 400 + 400 + 400 + 128 * 6) * sizeof(float);
    const size_t sm_att     = (size_t)(128 * 401 + 400 + 128) * sizeof(float);

    // Idempotent; errors ignored (attribute persists from the pre-capture correctness call).
    cudaFuncSetAttribute(const_kernel,   cudaFuncAttributeMaxDynamicSharedMemorySize, (int)sm_const);
    cudaFuncSetAttribute(spatial_kernel, cudaFuncAttributeMaxDynamicSharedMemorySize, (int)sm_spatial);
    cudaFuncSetAttribute(att_kernel,     cudaFuncAttributeMaxDynamicSharedMemorySize, (int)sm_att);

    prep_kernel<<<64, 256>>>(wr2, w2);
    feat_kernel<<<256, 128>>>(x, w1, g1, b1, m1, v1);
    const_kernel<<<400, 128, sm_const>>>(wr1, gr1, br1, mr1, vr1,
                                         gr2, br2, mr2, vr2,
                                         wr3, gr3, br3, mr3, vr3);
    spatial_kernel<<<400, 256, sm_spatial>>>(wr1, gr1, br1, mr1, vr1,
                                             gr2, br2, mr2, vr2,
                                             wr3, gr3, br3, mr3, vr3);
    att_kernel<<<100, 128, sm_att>>>(x, g2, b2, m2, v2, out);
}

// round 4
// speedup vs baseline: 2.5655x; 2.5655x over previous
#include <cuda_runtime.h>
#include <cstdint>

#define EPS 1e-5f

// ---------------- scratch (no allocations allowed) ----------------
static __device__ float g_featC[2 * 128 * 400];             // [b][c][i]
static __device__ float g_scores[2 * 400 * 400];            // [b][s][p]
static __device__ float g_W2sum[9 * 128 * 128];             // [cls][o_in][o_out]
static __device__ float g_w2T[128 * 128];                   // [c][co]
static __device__ __align__(16) float g_wA[9 * 128 * 128];  // [tap][k=in][m=out], tf32-rounded

__device__ __forceinline__ float silu_f(float y) {
    return y * (1.0f / (1.0f + __expf(-y)));
}
__device__ __forceinline__ float tf32r(float x) {
    uint32_t r;
    asm("cvt.rna.tf32.f32 %0, %1;" : "=r"(r) : "f"(x));
    return __uint_as_float(r);
}
__device__ __forceinline__ void mma_tf32(float* d, uint32_t a0, uint32_t a1, uint32_t a2, uint32_t a3,
                                         uint32_t b0, uint32_t b1) {
    asm volatile(
        "mma.sync.aligned.m16n8k8.row.col.f32.tf32.tf32.f32 "
        "{%0,%1,%2,%3}, {%4,%5,%6,%7}, {%8,%9}, {%0,%1,%2,%3};\n"
        : "+f"(d[0]), "+f"(d[1]), "+f"(d[2]), "+f"(d[3])
        : "r"(a0), "r"(a1), "r"(a2), "r"(a3), "r"(b0), "r"(b1));
}

// ---------------- prep: weight rearrangements ----------------
__global__ void prep_kernel(const float* __restrict__ wr2, const float* __restrict__ w2) {
    int t = blockIdx.x * blockDim.x + threadIdx.x;
    if (t >= 128 * 128) return;
    int op = t >> 7;   // out channel
    int o  = t & 127;  // in channel
    float w[9];
#pragma unroll
    for (int tap = 0; tap < 9; tap++) {
        w[tap] = wr2[(op * 128 + o) * 9 + tap];
        g_wA[(tap * 128 + o) * 128 + op] = tf32r(w[tap]);   // [tap][k][m]
    }
#pragma unroll
    for (int hc = 0; hc < 3; hc++) {
#pragma unroll
        for (int wc = 0; wc < 3; wc++) {
            float s = 0.f;
#pragma unroll
            for (int dh = 0; dh < 3; dh++) {
                if (hc == 0 && dh == 0) continue;
                if (hc == 2 && dh == 2) continue;
#pragma unroll
                for (int dw = 0; dw < 3; dw++) {
                    if (wc == 0 && dw == 0) continue;
                    if (wc == 2 && dw == 2) continue;
                    s += w[dh * 3 + dw];
                }
            }
            g_W2sum[((hc * 3 + wc) * 128 + o) * 128 + op] = s;
        }
    }
    g_w2T[o * 128 + op] = w2[op * 128 + o];
}

// ---------------- feat = CBS(x, w1), channel-major ----------------
__global__ void feat_kernel(const float* __restrict__ x, const float* __restrict__ w1,
                            const float* __restrict__ g1, const float* __restrict__ b1,
                            const float* __restrict__ m1, const float* __restrict__ v1) {
    __shared__ float wrow[128];
    int bc = blockIdx.x;
    int b = bc >> 7, c = bc & 127;
    int tid = threadIdx.x;
    wrow[tid] = w1[c * 128 + tid];
    __syncthreads();
    float a  = g1[c] * rsqrtf(v1[c] + EPS);
    float cc = b1[c] - m1[c] * a;
    for (int i = tid; i < 400; i += 128) {
        float s = 0.f;
#pragma unroll 8
        for (int cin = 0; cin < 128; cin++)
            s += wrow[cin] * x[(b * 128 + cin) * 400 + i];
        g_featC[(b * 128 + c) * 400 + i] = silu_f(a * s + cc);
    }
}

// ---------------- samples s < 200 : spatially constant ----------------
__global__ void const_kernel(const float* __restrict__ wr1,
                             const float* __restrict__ gr1, const float* __restrict__ br1,
                             const float* __restrict__ mr1, const float* __restrict__ vr1,
                             const float* __restrict__ gr2, const float* __restrict__ br2,
                             const float* __restrict__ mr2, const float* __restrict__ vr2,
                             const float* __restrict__ wr3,
                             const float* __restrict__ gr3, const float* __restrict__ br3,
                             const float* __restrict__ mr3, const float* __restrict__ vr3) {
    extern __shared__ float sm[];
    float* wr1s = sm;                    // 128 * 257
    float* fwin = wr1s + 128 * 257;      // 256
    float* vbuf = fwin + 256;            // 128
    float* zbuf = vbuf + 128;            // 128
    float* scb  = zbuf + 128;            // 16

    int blk = blockIdx.x;
    int b = blk / 200, s = blk % 200;
    int tid = threadIdx.x;

    for (int idx = tid; idx < 128 * 256; idx += 128) {
        int o = idx >> 8, u = idx & 255;
        wr1s[o * 257 + u] = wr1[idx];
    }
    fwin[tid]       = g_featC[b * 51200 + s * 256 + tid];
    fwin[tid + 128] = g_featC[b * 51200 + s * 256 + 128 + tid];
    __syncthreads();

    int o = tid;
    float K = 0.f;
#pragma unroll 8
    for (int u = 0; u < 256; u++) K += wr1s[o * 257 + u] * fwin[u];
    float a1 = gr1[o] * rsqrtf(vr1[o] + EPS);
    float c1 = br1[o] - mr1[o] * a1;
    vbuf[o] = silu_f(a1 * K + c1);
    __syncthreads();

    float a2 = gr2[o] * rsqrtf(vr2[o] + EPS);
    float c2 = br2[o] - mr2[o] * a2;
    float w3 = wr3[o];
    float a3 = gr3[0] * rsqrtf(vr3[0] + EPS);
    float c3 = br3[0] - mr3[0] * a3;

    for (int cls = 0; cls < 9; cls++) {
        float z = 0.f;
#pragma unroll 8
        for (int oo = 0; oo < 128; oo++)
            z += g_W2sum[(cls * 128 + oo) * 128 + o] * vbuf[oo];
        float zz = silu_f(a2 * z + c2);
        zbuf[o] = w3 * zz;
        __syncthreads();
        for (int off = 64; off > 0; off >>= 1) {
            if (o < off) zbuf[o] += zbuf[o + off];
            __syncthreads();
        }
        if (o == 0) scb[cls] = silu_f(a3 * zbuf[0] + c3);
        __syncthreads();
    }

    for (int p = tid; p < 400; p += 128) {
        int h = p / 20, w = p % 20;
        int hc = (h == 0) ? 0 : ((h == 19) ? 2 : 1);
        int wc = (w == 0) ? 0 : ((w == 19) ? 2 : 1);
        g_scores[(b * 400 + s) * 400 + p] = scb[hc * 3 + wc];
    }
}

// ---------------- samples s >= 200 : mma.sync tf32 implicit conv ----------------
// smem float offsets
#define F_Y1   0                  // 128 ch * 292 floats (12r x 24c padded, stride 292)
#define F_AS   37376              // 128 k * 132 (padded)
#define F_FA   54272              // 400
#define F_FB   54672              // 400
#define F_AL   55072
#define F_BE   55200
#define F_A1   55328
#define F_C1   55456
#define F_A2   55584
#define F_C2   55712
#define F_W3   55840
#define F_PART 55968              // 2 * 256
#define F_TOT  56480              // floats -> 225920 bytes

__global__ __launch_bounds__(256)
void spatial_mma_kernel(const float* __restrict__ wr1,
                        const float* __restrict__ gr1, const float* __restrict__ br1,
                        const float* __restrict__ mr1, const float* __restrict__ vr1,
                        const float* __restrict__ gr2, const float* __restrict__ br2,
                        const float* __restrict__ mr2, const float* __restrict__ vr2,
                        const float* __restrict__ wr3,
                        const float* __restrict__ gr3, const float* __restrict__ br3,
                        const float* __restrict__ mr3, const float* __restrict__ vr3) {
    extern __shared__ __align__(16) float smf[];
    float* y1s = smf + F_Y1;
    float* As  = smf + F_AS;
    float* FA  = smf + F_FA;
    float* FB  = smf + F_FB;
    float* AL  = smf + F_AL;
    float* BE  = smf + F_BE;
    float* A1S = smf + F_A1;
    float* C1S = smf + F_C1;
    float* A2S = smf + F_A2;
    float* C2S = smf + F_C2;
    float* W3S = smf + F_W3;
    float* PART = smf + F_PART;

    int blk = blockIdx.x;            // 800 = 2b * 200s * 2half
    int b = blk / 400;
    int rem = blk - b * 400;
    int s = 200 + (rem >> 1);
    int half = rem & 1;
    int tid = threadIdx.x;           // 256
    int wid = tid >> 5;
    int lane = tid & 31;

    // zero y1 region (borders/pads stay zero)
    for (int i = tid; i < 37376 / 4; i += 256)
        ((float4*)y1s)[i] = make_float4(0.f, 0.f, 0.f, 0.f);

    // per-sample rank-2 decomposition of the r1 1x1 conv
    int t0 = s * 256;
    int r0 = t0 % 400;
    int usplit = 400 - r0;
    if (usplit > 256) usplit = 256;
    int chA = t0 / 400 - 128;
    int chB = (usplit >= 256) ? chA : (chA + 1);

    if (tid < 128) {
        float a = 0.f;
#pragma unroll 8
        for (int u = 0; u < usplit; u++) a += wr1[tid * 256 + u];
        AL[tid] = a;
    } else {
        int o = tid - 128;
        float bs = 0.f;
        for (int u = usplit; u < 256; u++) bs += wr1[o * 256 + u];
        BE[o] = bs;
        float a1 = gr1[o] * rsqrtf(vr1[o] + EPS);
        A1S[o] = a1;
        C1S[o] = br1[o] - mr1[o] * a1;
        float a2 = gr2[o] * rsqrtf(vr2[o] + EPS);
        A2S[o] = a2;
        C2S[o] = br2[o] - mr2[o] * a2;
        W3S[o] = wr3[o];
    }
    for (int p = tid; p < 400; p += 256) {
        FA[p] = g_featC[b * 51200 + chA * 400 + p];
        FB[p] = g_featC[b * 51200 + chB * 400 + p];
    }
    __syncthreads();

    // build y1 (tf32-rounded): 12 rows (with halo) x 20 cols, all 128 channels
    if (tid < 240) {
        int r = tid / 20, w = tid % 20;
        int gh = half * 10 + r - 1;
        if (gh >= 0 && gh < 20) {
            float fa = FA[gh * 20 + w];
            float fb = FB[gh * 20 + w];
            int base = r * 24 + w + 1;
#pragma unroll 4
            for (int o = 0; o < 128; o++) {
                float y = silu_f(A1S[o] * (AL[o] * fa + BE[o] * fb) + C1S[o]);
                y1s[o * 292 + base] = tf32r(y);
            }
        }
    }

    // register-blocked mma: warp = (wm in M{0,1} x wn in N{0..3})
    int wm = wid >> 2;
    int wn = wid & 3;
    int mb = wm * 64;                 // warp M base (64 rows = 4 m16 tiles)
    int nb = wn * 64;                 // warp N base (64 padded cols = 8 n8 tiles)
    int la = lane & 3;
    int lg = lane >> 2;

    float acc[4][8][4];
#pragma unroll
    for (int mt = 0; mt < 4; mt++)
#pragma unroll
        for (int nt = 0; nt < 8; nt++)
#pragma unroll
            for (int c = 0; c < 4; c++) acc[mt][nt][c] = 0.f;

    for (int tap = 0; tap < 9; tap++) {
        __syncthreads();   // previous tap's A reads done (and first-iter: y1 ready)
        // stage A[tap] -> smem [k][132]
        {
            const float4* src = (const float4*)(g_wA + tap * 16384);
            for (int i = tid; i < 4096; i += 256) {
                int k = i >> 5, q = i & 31;
                float4 v = src[i];
                *(float4*)(As + k * 132 + q * 4) = v;
            }
        }
        __syncthreads();

        int dh = tap / 3, dw = tap - dh * 3;
        int boff = dh * 24 + dw;

#pragma unroll 1
        for (int kk = 0; kk < 16; kk++) {
            int k0 = kk * 8;
            // B fragments: 8 N-tiles
            uint32_t bv0[8], bv1[8];
            const float* brow0 = y1s + (k0 + la) * 292 + nb + lg + boff;
#pragma unroll
            for (int nt = 0; nt < 8; nt++) {
                bv0[nt] = __float_as_uint(brow0[nt * 8]);
                bv1[nt] = __float_as_uint(brow0[nt * 8 + 4 * 292]);
            }
            const float* arow0 = As + (k0 + la) * 132 + mb + lg;
#pragma unroll
            for (int mt = 0; mt < 4; mt++) {
                uint32_t a0 = __float_as_uint(arow0[mt * 16]);
                uint32_t a1 = __float_as_uint(arow0[mt * 16 + 8]);
                uint32_t a2 = __float_as_uint(arow0[mt * 16 + 4 * 132]);
                uint32_t a3 = __float_as_uint(arow0[mt * 16 + 4 * 132 + 8]);
#pragma unroll
                for (int nt = 0; nt < 8; nt++)
                    mma_tf32(acc[mt][nt], a0, a1, a2, a3, bv0[nt], bv1[nt]);
            }
        }
    }

    // epilogue: bn2+silu, r3 (128->1) reduce, bn3+silu -> scores
    float a3 = gr3[0] * rsqrtf(vr3[0] + EPS);
    float c3 = br3[0] - mr3[0] * a3;

    float pnt[8][2];
#pragma unroll
    for (int nt = 0; nt < 8; nt++) { pnt[nt][0] = 0.f; pnt[nt][1] = 0.f; }

#pragma unroll
    for (int mt = 0; mt < 4; mt++) {
#pragma unroll
        for (int rs = 0; rs < 2; rs++) {
            int m = mb + mt * 16 + rs * 8 + lg;
            float a2m = A2S[m], c2m = C2S[m], w3m = W3S[m];
#pragma unroll
            for (int nt = 0; nt < 8; nt++) {
#pragma unroll
                for (int cc = 0; cc < 2; cc++) {
                    float z = silu_f(a2m * acc[mt][nt][cc + 2 * rs] + c2m);
                    pnt[nt][cc] += w3m * z;
                }
            }
        }
    }

#pragma unroll
    for (int nt = 0; nt < 8; nt++) {
#pragma unroll
        for (int cc = 0; cc < 2; cc++) {
            float v = pnt[nt][cc];
            v += __shfl_xor_sync(0xffffffffu, v, 4);
            v += __shfl_xor_sync(0xffffffffu, v, 8);
            v += __shfl_xor_sync(0xffffffffu, v, 16);
            if (lane < 4)
                PART[wm * 256 + nb + nt * 8 + 2 * lane + cc] = v;
        }
    }
    __syncthreads();

    if (tid < 240) {
        int wcol = tid % 24;
        if (wcol < 20) {
            int hl = tid / 24;
            float v = PART[tid] + PART[256 + tid];
            int h = half * 10 + hl;
            g_scores[(b * 400 + s) * 400 + h * 20 + wcol] = silu_f(a3 * v + c3);
        }
    }
}

// ---------------- attention bmm + conv2(1x1)+bn+silu + residual ----------------
__global__ void att_kernel(const float* __restrict__ x,
                           const float* __restrict__ g2, const float* __restrict__ b2,
                           const float* __restrict__ m2, const float* __restrict__ v2,
                           float* __restrict__ out) {
    extern __shared__ float sm[];
    float* featCs = sm;                    // 128*401
    float* srow   = featCs + 128 * 401;    // 400
    float* atts   = srow + 400;            // 128

    int blk = blockIdx.x;
    int b = blk / 50;
    int ib = (blk % 50) * 8;
    int tid = threadIdx.x;

    for (int idx = tid; idx < 128 * 400; idx += 128) {
        int c = idx / 400, j = idx - c * 400;
        featCs[c * 401 + j] = g_featC[b * 51200 + idx];
    }
    __syncthreads();

    float a  = g2[tid] * rsqrtf(v2[tid] + EPS);
    float cc = b2[tid] - m2[tid] * a;

    for (int r = 0; r < 8; r++) {
        int i = ib + r;
        __syncthreads();
        for (int j = tid; j < 400; j += 128)
            srow[j] = g_scores[(b * 400 + i) * 400 + j];
        __syncthreads();
        int c = tid;
        float acc = 0.f;
#pragma unroll 8
        for (int j = 0; j < 400; j++) acc += srow[j] * featCs[c * 401 + j];
        atts[c] = acc;
        __syncthreads();
        int co = tid;
        float y = 0.f;
#pragma unroll 8
        for (int k = 0; k < 128; k++) y += g_w2T[k * 128 + co] * atts[k];
        out[(b * 128 + co) * 400 + i] = silu_f(a * y + cc) + x[(b * 128 + co) * 400 + i];
    }
}

// ---------------- launcher ----------------
extern "C" void kernel_launch(void* const* d_in, const int* in_sizes, int n_in,
                              void* d_out, int out_size) {
    (void)in_sizes; (void)n_in; (void)out_size;
    const float* x   = (const float*)d_in[0];
    const float* w1  = (const float*)d_in[1];
    const float* g1  = (const float*)d_in[2];
    const float* b1  = (const float*)d_in[3];
    const float* m1  = (const float*)d_in[4];
    const float* v1  = (const float*)d_in[5];
    const float* w2  = (const float*)d_in[6];
    const float* g2  = (const float*)d_in[7];
    const float* b2  = (const float*)d_in[8];
    const float* m2  = (const float*)d_in[9];
    const float* v2  = (const float*)d_in[10];
    const float* wr1 = (const float*)d_in[11];
    const float* gr1 = (const float*)d_in[12];
    const float* br1 = (const float*)d_in[13];
    const float* mr1 = (const float*)d_in[14];
    const float* vr1 = (const float*)d_in[15];
    const float* wr2 = (const float*)d_in[16];
    const float* gr2 = (const float*)d_in[17];
    const float* br2 = (const float*)d_in[18];
    const float* mr2 = (const float*)d_in[19];
    const float* vr2 = (const float*)d_in[20];
    const float* wr3 = (const float*)d_in[21];
    const float* gr3 = (const float*)d_in[22];
    const float* br3 = (const float*)d_in[23];
    const float* mr3 = (const float*)d_in[24];
    const float* vr3 = (const float*)d_in[25];
    float* out = (float*)d_out;

    const size_t sm_const   = (size_t)(128 * 257 + 256 + 128 + 128 + 16) * sizeof(float);
    const size_t sm_att     = (size_t)(128 * 401 + 400 + 128) * sizeof(float);
    const size_t sm_spatial = (size_t)F_TOT * sizeof(float);   // 225920 B

    cudaFuncSetAttribute(const_kernel,       cudaFuncAttributeMaxDynamicSharedMemorySize, (int)sm_const);
    cudaFuncSetAttribute(spatial_mma_kernel, cudaFuncAttributeMaxDynamicSharedMemorySize, (int)sm_spatial);
    cudaFuncSetAttribute(att_kernel,         cudaFuncAttributeMaxDynamicSharedMemorySize, (int)sm_att);

    prep_kernel<<<64, 256>>>(wr2, w2);
    feat_kernel<<<256, 128>>>(x, w1, g1, b1, m1, v1);
    const_kernel<<<400, 128, sm_const>>>(wr1, gr1, br1, mr1, vr1,
                                         gr2, br2, mr2, vr2,
                                         wr3, gr3, br3, mr3, vr3);
    spatial_mma_kernel<<<800, 256, sm_spatial>>>(wr1, gr1, br1, mr1, vr1,
                                                 gr2, br2, mr2, vr2,
                                                 wr3, gr3, br3, mr3, vr3);
    att_kernel<<<100, 128, sm_att>>>(x, g2, b2, m2, v2, out);
}

// round 5
// speedup vs baseline: 5.4155x; 2.1109x over previous
#include <cuda_runtime.h>
#include <cuda_fp16.h>
#include <cstdint>

#define EPS 1e-5f

// ---------------- scratch (no allocations allowed) ----------------
static __device__ float g_featC[2 * 128 * 400];             // [b][c][i]; flat view = [u=400][256]
static __device__ float g_scores[2 * 400 * 400];            // [b][s][p]
static __device__ float g_W2sum[9 * 128 * 128];             // [cls][o_in][o_out]
static __device__ float g_w2T[128 * 128];                   // [c][co]
static __device__ float g_AL[200 * 128];                    // [s-200][o]
static __device__ float g_BE[200 * 128];
static __device__ __align__(16) uint32_t g_wAf[18432 * 4];  // f16 A fragments [tap][wm][kk][mt][lane][4xb32]

__device__ __forceinline__ float silu_f(float y) {
    return y * (1.0f / (1.0f + __expf(-y)));
}
__device__ __forceinline__ void mma_f16(float* d, uint32_t a0, uint32_t a1, uint32_t a2, uint32_t a3,
                                        uint32_t b0, uint32_t b1) {
    asm volatile(
        "mma.sync.aligned.m16n8k16.row.col.f32.f16.f16.f32 "
        "{%0,%1,%2,%3}, {%4,%5,%6,%7}, {%8,%9}, {%0,%1,%2,%3};\n"
        : "+f"(d[0]), "+f"(d[1]), "+f"(d[2]), "+f"(d[3])
        : "r"(a0), "r"(a1), "r"(a2), "r"(a3), "r"(b0), "r"(b1));
}

// ---------------- prep: W2sum + w2T ----------------
__global__ void prep_kernel(const float* __restrict__ wr2, const float* __restrict__ w2) {
    int t = blockIdx.x * blockDim.x + threadIdx.x;
    if (t >= 128 * 128) return;
    int op = t >> 7;
    int o  = t & 127;
    float w[9];
#pragma unroll
    for (int tap = 0; tap < 9; tap++) w[tap] = wr2[(op * 128 + o) * 9 + tap];
#pragma unroll
    for (int hc = 0; hc < 3; hc++) {
#pragma unroll
        for (int wc = 0; wc < 3; wc++) {
            float s = 0.f;
#pragma unroll
            for (int dh = 0; dh < 3; dh++) {
                if (hc == 0 && dh == 0) continue;
                if (hc == 2 && dh == 2) continue;
#pragma unroll
                for (int dw = 0; dw < 3; dw++) {
                    if (wc == 0 && dw == 0) continue;
                    if (wc == 2 && dw == 2) continue;
                    s += w[dh * 3 + dw];
                }
            }
            g_W2sum[((hc * 3 + wc) * 128 + o) * 128 + op] = s;
        }
    }
    g_w2T[o * 128 + op] = w2[op * 128 + o];
}

// ---------------- prep: f16 A fragments for m16n8k16 ----------------
__global__ void prep_frag_kernel(const float* __restrict__ wr2) {
    int t = blockIdx.x * blockDim.x + threadIdx.x;
    if (t >= 18432) return;
    int lane = t & 31;
    int mt   = (t >> 5) & 3;
    int kk   = (t >> 7) & 7;
    int wm   = (t >> 10) & 1;
    int tap  = t >> 11;
    int m0 = wm * 64 + mt * 16 + (lane >> 2);
    int k0 = kk * 16 + 2 * (lane & 3);
    // W[m][k] = wr2[(m*128+k)*9 + tap]
    float f[8];
    f[0] = wr2[(m0 * 128 + k0) * 9 + tap];
    f[1] = wr2[(m0 * 128 + k0 + 1) * 9 + tap];
    f[2] = wr2[((m0 + 8) * 128 + k0) * 9 + tap];
    f[3] = wr2[((m0 + 8) * 128 + k0 + 1) * 9 + tap];
    f[4] = wr2[(m0 * 128 + k0 + 8) * 9 + tap];
    f[5] = wr2[(m0 * 128 + k0 + 9) * 9 + tap];
    f[6] = wr2[((m0 + 8) * 128 + k0 + 8) * 9 + tap];
    f[7] = wr2[((m0 + 8) * 128 + k0 + 9) * 9 + tap];
    uint32_t u[4];
#pragma unroll
    for (int i = 0; i < 4; i++) {
        uint32_t lo = __half_as_ushort(__float2half_rn(f[2 * i]));
        uint32_t hi = __half_as_ushort(__float2half_rn(f[2 * i + 1]));
        u[i] = lo | (hi << 16);
    }
    ((uint4*)g_wAf)[t] = make_uint4(u[0], u[1], u[2], u[3]);
}

// ---------------- prep: per-sample alpha/beta via row prefix scan ----------------
__global__ void ab_kernel(const float* __restrict__ wr1) {
    __shared__ float warpsum[8];
    __shared__ float Pex[258];
    int o = blockIdx.x;          // 0..127
    int t = threadIdx.x;         // 256
    int lane = t & 31, w = t >> 5;
    float v = wr1[o * 256 + t];
    float x = v;
#pragma unroll
    for (int d = 1; d < 32; d <<= 1) {
        float y = __shfl_up_sync(0xffffffffu, x, d);
        if (lane >= d) x += y;
    }
    if (lane == 31) warpsum[w] = x;
    __syncthreads();
    if (t == 0) {
        float r = 0.f;
#pragma unroll
        for (int i = 0; i < 8; i++) { float tmp = warpsum[i]; warpsum[i] = r; r += tmp; }
        Pex[256] = r;   // total
    }
    __syncthreads();
    float incl = x + warpsum[w];
    Pex[t] = incl - v;
    __syncthreads();
    if (t < 200) {
        int s = 200 + t;
        int r0 = (s * 256) % 400;
        int usplit = 400 - r0;
        if (usplit > 256) usplit = 256;
        float total = Pex[256];
        float al = (usplit == 256) ? total : Pex[usplit];
        g_AL[t * 128 + o] = al;
        g_BE[t * 128 + o] = total - al;
    }
}

// ---------------- feat = CBS(x, w1), channel-major ----------------
__global__ void feat_kernel(const float* __restrict__ x, const float* __restrict__ w1,
                            const float* __restrict__ g1, const float* __restrict__ b1,
                            const float* __restrict__ m1, const float* __restrict__ v1) {
    __shared__ float wrow[128];
    int bc = blockIdx.x;
    int b = bc >> 7, c = bc & 127;
    int tid = threadIdx.x;
    wrow[tid] = w1[c * 128 + tid];
    __syncthreads();
    float a  = g1[c] * rsqrtf(v1[c] + EPS);
    float cc = b1[c] - m1[c] * a;
    for (int i = tid; i < 400; i += 128) {
        float s = 0.f;
#pragma unroll 8
        for (int cin = 0; cin < 128; cin++)
            s += wrow[cin] * x[(b * 128 + cin) * 400 + i];
        g_featC[(b * 128 + c) * 400 + i] = silu_f(a * s + cc);
    }
}

// ---------------- samples s < 200 : batched (8 samples / CTA) ----------------
#define CW_WR1  0                // 128*257
#define CW_FWIN 32896            // 8*260
#define CW_V    34976            // 8*132
#define CW_RED  36032            // 4*72
#define CW_SCB  36320            // 72
#define CW_TOT  36416            // floats

__global__ __launch_bounds__(128)
void const_kernel(const float* __restrict__ wr1,
                  const float* __restrict__ gr1, const float* __restrict__ br1,
                  const float* __restrict__ mr1, const float* __restrict__ vr1,
                  const float* __restrict__ gr2, const float* __restrict__ br2,
                  const float* __restrict__ mr2, const float* __restrict__ vr2,
                  const float* __restrict__ wr3,
                  const float* __restrict__ gr3, const float* __restrict__ br3,
                  const float* __restrict__ mr3, const float* __restrict__ vr3) {
    extern __shared__ float sm[];
    float* wr1s = sm + CW_WR1;
    float* fwin = sm + CW_FWIN;
    float* V    = sm + CW_V;
    float* red  = sm + CW_RED;
    float* scb  = sm + CW_SCB;

    int blk = blockIdx.x;            // 50 blocks, 8 samples each
    int u0 = blk * 8;
    int tid = threadIdx.x;           // 128
    int lane = tid & 31, wrp = tid >> 5;

    for (int idx = tid; idx < 128 * 256; idx += 128) {
        int o = idx >> 8, u = idx & 255;
        wr1s[o * 257 + u] = wr1[idx];
    }
    for (int idx = tid; idx < 8 * 256; idx += 128) {
        int su = idx >> 8, j = idx & 255;
        fwin[su * 260 + j] = g_featC[(u0 + su) * 256 + j];
    }
    __syncthreads();

    int o = tid;
    {
        float acc[8];
#pragma unroll
        for (int su = 0; su < 8; su++) acc[su] = 0.f;
#pragma unroll 4
        for (int j = 0; j < 256; j++) {
            float wv = wr1s[o * 257 + j];
#pragma unroll
            for (int su = 0; su < 8; su++) acc[su] += wv * fwin[su * 260 + j];
        }
        float a1 = gr1[o] * rsqrtf(vr1[o] + EPS);
        float c1 = br1[o] - mr1[o] * a1;
#pragma unroll
        for (int su = 0; su < 8; su++) V[su * 132 + o] = silu_f(a1 * acc[su] + c1);
    }
    __syncthreads();

    float a2 = gr2[o] * rsqrtf(vr2[o] + EPS);
    float c2 = br2[o] - mr2[o] * a2;
    float w3 = wr3[o];
    float a3 = gr3[0] * rsqrtf(vr3[0] + EPS);
    float c3 = br3[0] - mr3[0] * a3;

    float z[72];
#pragma unroll
    for (int i = 0; i < 72; i++) z[i] = 0.f;

#pragma unroll 1
    for (int oo = 0; oo < 128; oo++) {
        float vv[8];
#pragma unroll
        for (int su = 0; su < 8; su++) vv[su] = V[su * 132 + oo];
#pragma unroll
        for (int cls = 0; cls < 9; cls++) {
            float wv = g_W2sum[(cls * 128 + oo) * 128 + o];
#pragma unroll
            for (int su = 0; su < 8; su++) z[cls * 8 + su] += wv * vv[su];
        }
    }

#pragma unroll
    for (int i = 0; i < 72; i++) {
        float p = w3 * silu_f(a2 * z[i] + c2);
        p += __shfl_xor_sync(0xffffffffu, p, 1);
        p += __shfl_xor_sync(0xffffffffu, p, 2);
        p += __shfl_xor_sync(0xffffffffu, p, 4);
        p += __shfl_xor_sync(0xffffffffu, p, 8);
        p += __shfl_xor_sync(0xffffffffu, p, 16);
        if (lane == 0) red[wrp * 72 + i] = p;
    }
    __syncthreads();
    if (tid < 72) {
        float tot = red[tid] + red[72 + tid] + red[144 + tid] + red[216 + tid];
        scb[tid] = silu_f(a3 * tot + c3);
    }
    __syncthreads();

    for (int idx = tid; idx < 8 * 400; idx += 128) {
        int su = idx / 400, p = idx % 400;
        int h = p / 20, w = p % 20;
        int hc = (h == 0) ? 0 : ((h == 19) ? 2 : 1);
        int wc = (w == 0) ? 0 : ((w == 19) ? 2 : 1);
        int u = u0 + su;
        int b = u / 200, s = u % 200;
        g_scores[(b * 400 + s) * 400 + p] = scb[(hc * 3 + wc) * 8 + su];
    }
}

// ---------------- samples s >= 200 : f16 mma implicit conv, quarter-sample CTAs ----------------
// smem byte offsets
#define SP_Y      0               // 180 rows x 136 halves  = 48960 B
#define SP_AS     48960           // 2048 uint4 = 32768 B
#define SP_CONST  81728           // 7 x 128 floats
#define SP_FW     85312           // FAw 160 + FBw 160 floats
#define SP_PART   86592           // 256 floats
#define SP_TOT    87616

__global__ __launch_bounds__(256, 2)
void spatial_f16_kernel(const float* __restrict__ gr1, const float* __restrict__ br1,
                        const float* __restrict__ mr1, const float* __restrict__ vr1,
                        const float* __restrict__ gr2, const float* __restrict__ br2,
                        const float* __restrict__ mr2, const float* __restrict__ vr2,
                        const float* __restrict__ wr3,
                        const float* __restrict__ gr3, const float* __restrict__ br3,
                        const float* __restrict__ mr3, const float* __restrict__ vr3) {
    extern __shared__ __align__(16) char smem[];
    __half* Yh  = (__half*)(smem + SP_Y);
    uint4* ASu  = (uint4*)(smem + SP_AS);
    float* A1S  = (float*)(smem + SP_CONST);
    float* C1S  = A1S + 128;
    float* A2S  = C1S + 128;
    float* C2S  = A2S + 128;
    float* W3S  = C2S + 128;
    float* ALs  = W3S + 128;
    float* BEs  = ALs + 128;
    float* FAw  = (float*)(smem + SP_FW);
    float* FBw  = FAw + 160;
    float* PART = (float*)(smem + SP_PART);

    int blk = blockIdx.x;                 // 1600 = 2b * 200s * 4q
    int b = blk / 800;
    int rem = blk - b * 800;
    int sIdx = rem >> 2;                  // 0..199
    int s = 200 + sIdx;
    int q = rem & 3;                      // quarter: output rows q*5 .. q*5+4
    int tid = threadIdx.x;
    int wid = tid >> 5;
    int lane = tid & 31;
    int la = lane & 3, lg = lane >> 2;

    // zero Y (180*136 halves = 3060 uint4)
    {
        uint4 z4 = make_uint4(0, 0, 0, 0);
        uint4* Yz = (uint4*)(smem + SP_Y);
        for (int i = tid; i < 3060; i += 256) Yz[i] = z4;
    }

    int t0 = s * 256;
    int r0 = t0 % 400;
    int usplit = 400 - r0;
    if (usplit > 256) usplit = 256;
    int chA = t0 / 400 - 128;
    int chB = (usplit >= 256) ? chA : (chA + 1);

    if (tid < 128) {
        int o = tid;
        float a1 = gr1[o] * rsqrtf(vr1[o] + EPS);
        A1S[o] = a1;
        C1S[o] = br1[o] - mr1[o] * a1;
        float a2 = gr2[o] * rsqrtf(vr2[o] + EPS);
        A2S[o] = a2;
        C2S[o] = br2[o] - mr2[o] * a2;
        W3S[o] = wr3[o];
        ALs[o] = g_AL[sIdx * 128 + o];
        BEs[o] = g_BE[sIdx * 128 + o];
    }
    // feature window: 7 rows (with halo) x 20 cols for chA and chB
    for (int idx = tid; idx < 280; idx += 256) {
        int arr = idx / 140, pos = idx % 140;
        int rw = pos / 20, gw = pos % 20;
        int gh = q * 5 - 1 + rw;
        float v = 0.f;
        if (gh >= 0 && gh < 20)
            v = g_featC[b * 51200 + (arr ? chB : chA) * 400 + gh * 20 + gw];
        (arr ? FBw : FAw)[pos] = v;
    }
    __syncthreads();

    // build y1T[n_row][ch] as f16, n_row = rw*24 + gw + 1
    for (int it = 0; it < 2; it++) {
        int idx = tid + it * 256;
        if (idx < 280) {
            int chh = idx / 140, pos = idx % 140;
            int rw = pos / 20, gw = pos % 20;
            int gh = q * 5 - 1 + rw;
            if (gh >= 0 && gh < 20) {
                float fa = FAw[pos], fb = FBw[pos];
                int rowoff = (rw * 24 + gw + 1) * 136;
#pragma unroll 8
                for (int o2 = 0; o2 < 32; o2++) {
                    int o = chh * 64 + o2 * 2;
                    float y0 = silu_f(A1S[o] * (ALs[o] * fa + BEs[o] * fb) + C1S[o]);
                    float y1 = silu_f(A1S[o + 1] * (ALs[o + 1] * fa + BEs[o + 1] * fb) + C1S[o + 1]);
                    *(__half2*)(Yh + rowoff + o) = __floats2half2_rn(y0, y1);
                }
            }
        }
    }

    int wm = wid >> 2;                // 0,1 : M half
    int wn = wid & 3;                 // 0..3 : N quarter (32 cols)
    int nb = wn * 32;

    float acc[4][4][4];
#pragma unroll
    for (int mt = 0; mt < 4; mt++)
#pragma unroll
        for (int nt = 0; nt < 4; nt++)
#pragma unroll
            for (int c = 0; c < 4; c++) acc[mt][nt][c] = 0.f;

    for (int tap = 0; tap < 9; tap++) {
        // stage A fragments for this tap (32KB)
        {
            const uint4* src = ((const uint4*)g_wAf) + tap * 2048;
            for (int i = tid; i < 2048; i += 256) ASu[i] = src[i];
        }
        __syncthreads();

        int dh = tap / 3, dw = tap - dh * 3;
        int boff = dh * 24 + dw;
        int base_n = nb + lg + boff;
        const uint32_t* Bcol;

#pragma unroll
        for (int kk = 0; kk < 8; kk++) {
            Bcol = (const uint32_t*)(Yh + kk * 16 + 2 * la);
            uint32_t bv0[4], bv1[4];
#pragma unroll
            for (int nt = 0; nt < 4; nt++) {
                int row = base_n + nt * 8;
                bv0[nt] = Bcol[row * 68];
                bv1[nt] = Bcol[row * 68 + 4];
            }
#pragma unroll
            for (int mt = 0; mt < 4; mt++) {
                uint4 av = ASu[((wm * 8 + kk) * 4 + mt) * 32 + lane];
#pragma unroll
                for (int nt = 0; nt < 4; nt++)
                    mma_f16(acc[mt][nt], av.x, av.y, av.z, av.w, bv0[nt], bv1[nt]);
            }
        }
        __syncthreads();   // A reads done before next stage
    }

    // epilogue: bn2+silu, r3 reduce over m, bn3+silu -> scores
    float a3 = gr3[0] * rsqrtf(vr3[0] + EPS);
    float c3 = br3[0] - mr3[0] * a3;

    float pnt[4][2];
#pragma unroll
    for (int nt = 0; nt < 4; nt++) { pnt[nt][0] = 0.f; pnt[nt][1] = 0.f; }

#pragma unroll
    for (int mt = 0; mt < 4; mt++) {
#pragma unroll
        for (int rs = 0; rs < 2; rs++) {
            int m = wm * 64 + mt * 16 + rs * 8 + lg;
            float a2m = A2S[m], c2m = C2S[m], w3m = W3S[m];
#pragma unroll
            for (int nt = 0; nt < 4; nt++) {
#pragma unroll
                for (int cc = 0; cc < 2; cc++) {
                    float zv = silu_f(a2m * acc[mt][nt][rs * 2 + cc] + c2m);
                    pnt[nt][cc] += w3m * zv;
                }
            }
        }
    }
#pragma unroll
    for (int nt = 0; nt < 4; nt++) {
#pragma unroll
        for (int cc = 0; cc < 2; cc++) {
            float v = pnt[nt][cc];
            v += __shfl_xor_sync(0xffffffffu, v, 4);
            v += __shfl_xor_sync(0xffffffffu, v, 8);
            v += __shfl_xor_sync(0xffffffffu, v, 16);
            if (lane < 4)
                PART[wm * 128 + nb + nt * 8 + 2 * lane + cc] = v;
        }
    }
    __syncthreads();

    if (tid < 128) {
        int n = tid;
        int hl = n / 24, wc = n % 24;
        if (hl < 5 && wc < 20) {
            float v = PART[n] + PART[128 + n];
            int h = q * 5 + hl;
            g_scores[(b * 400 + s) * 400 + h * 20 + wc] = silu_f(a3 * v + c3);
        }
    }
}

// ---------------- attention bmm + conv2(1x1)+bn+silu + residual ----------------
__global__ void att_kernel(const float* __restrict__ x,
                           const float* __restrict__ g2, const float* __restrict__ b2,
                           const float* __restrict__ m2, const float* __restrict__ v2,
                           float* __restrict__ out) {
    extern __shared__ float sm[];
    float* featCs = sm;                    // 128*401
    float* srow   = featCs + 128 * 401;    // 400
    float* atts   = srow + 400;            // 128

    int blk = blockIdx.x;
    int b = blk / 50;
    int ib = (blk % 50) * 8;
    int tid = threadIdx.x;

    for (int idx = tid; idx < 128 * 400; idx += 128) {
        int c = idx / 400, j = idx - c * 400;
        featCs[c * 401 + j] = g_featC[b * 51200 + idx];
    }
    __syncthreads();

    float a  = g2[tid] * rsqrtf(v2[tid] + EPS);
    float cc = b2[tid] - m2[tid] * a;

    for (int r = 0; r < 8; r++) {
        int i = ib + r;
        __syncthreads();
        for (int j = tid; j < 400; j += 128)
            srow[j] = g_scores[(b * 400 + i) * 400 + j];
        __syncthreads();
        int c = tid;
        float acc = 0.f;
#pragma unroll 8
        for (int j = 0; j < 400; j++) acc += srow[j] * featCs[c * 401 + j];
        atts[c] = acc;
        __syncthreads();
        int co = tid;
        float y = 0.f;
#pragma unroll 8
        for (int k = 0; k < 128; k++) y += g_w2T[k * 128 + co] * atts[k];
        out[(b * 128 + co) * 400 + i] = silu_f(a * y + cc) + x[(b * 128 + co) * 400 + i];
    }
}

// ---------------- launcher ----------------
extern "C" void kernel_launch(void* const* d_in, const int* in_sizes, int n_in,
                              void* d_out, int out_size) {
    (void)in_sizes; (void)n_in; (void)out_size;
    const float* x   = (const float*)d_in[0];
    const float* w1  = (const float*)d_in[1];
    const float* g1  = (const float*)d_in[2];
    const float* b1  = (const float*)d_in[3];
    const float* m1  = (const float*)d_in[4];
    const float* v1  = (const float*)d_in[5];
    const float* w2  = (const float*)d_in[6];
    const float* g2  = (const float*)d_in[7];
    const float* b2  = (const float*)d_in[8];
    const float* m2  = (const float*)d_in[9];
    const float* v2  = (const float*)d_in[10];
    const float* wr1 = (const float*)d_in[11];
    const float* gr1 = (const float*)d_in[12];
    const float* br1 = (const float*)d_in[13];
    const float* mr1 = (const float*)d_in[14];
    const float* vr1 = (const float*)d_in[15];
    const float* wr2 = (const float*)d_in[16];
    const float* gr2 = (const float*)d_in[17];
    const float* br2 = (const float*)d_in[18];
    const float* mr2 = (const float*)d_in[19];
    const float* vr2 = (const float*)d_in[20];
    const float* wr3 = (const float*)d_in[21];
    const float* gr3 = (const float*)d_in[22];
    const float* br3 = (const float*)d_in[23];
    const float* mr3 = (const float*)d_in[24];
    const float* vr3 = (const float*)d_in[25];
    float* out = (float*)d_out;

    const size_t sm_const = (size_t)CW_TOT * sizeof(float);          // ~145.7 KB
    const size_t sm_att   = (size_t)(128 * 401 + 400 + 128) * sizeof(float);

    cudaFuncSetAttribute(const_kernel,       cudaFuncAttributeMaxDynamicSharedMemorySize, (int)sm_const);
    cudaFuncSetAttribute(spatial_f16_kernel, cudaFuncAttributeMaxDynamicSharedMemorySize, SP_TOT);
    cudaFuncSetAttribute(att_kernel,         cudaFuncAttributeMaxDynamicSharedMemorySize, (int)sm_att);

    prep_kernel<<<64, 256>>>(wr2, w2);
    prep_frag_kernel<<<72, 256>>>(wr2);
    ab_kernel<<<128, 256>>>(wr1);
    feat_kernel<<<256, 128>>>(x, w1, g1, b1, m1, v1);
    spatial_f16_kernel<<<1600, 256, SP_TOT>>>(gr1, br1, mr1, vr1,
                                              gr2, br2, mr2, vr2,
                                              wr3, gr3, br3, mr3, vr3);
    const_kernel<<<50, 128, sm_const>>>(wr1, gr1, br1, mr1, vr1,
                                        gr2, br2, mr2, vr2,
                                        wr3, gr3, br3, mr3, vr3);
    att_kernel<<<100, 128, sm_att>>>(x, g2, b2, m2, v2, out);
}